// round 15
// baseline (speedup 1.0000x reference)
#include <cuda_runtime.h>
#include <cstdint>

// Problem constants
#define Bb 64
#define Cc 64
#define Tt 128
#define Vv 25
#define Rr 8
#define TSs 9
#define OUTo 64

typedef unsigned long long ull;

// Scratch (device globals — no allocation allowed)
__device__ float g_xbar[Bb * Cc * Vv];          // (b,c,v) mean over t
__device__ float g_rel[Bb * Rr * Vv * Vv];      // (b,r,vi)
__device__ float g_z[Bb * Cc * Tt * Vv];        // (b,c,t,v), tf32-rounded
__device__ unsigned g_w3t[OUTo * Cc];           // W3 pre-rounded to tf32 bits

// ---------- helpers ----------
__device__ __forceinline__ void cp_async16(float* smem_dst, const float* gmem_src) {
    unsigned s = (unsigned)__cvta_generic_to_shared(smem_dst);
    asm volatile("cp.async.cg.shared.global [%0], [%1], 16;\n" :: "r"(s), "l"(gmem_src));
}
template <int N> __device__ __forceinline__ void wait_group() {
    asm volatile("cp.async.wait_group %0;\n" :: "n"(N) : "memory");
}
__device__ __forceinline__ float to_tf32(float x) {
    unsigned u;
    asm("cvt.rna.tf32.f32 %0, %1;" : "=r"(u) : "f"(x));
    return __uint_as_float(u);
}
__device__ __forceinline__ void mma_tf32(float* c, const unsigned* a, const unsigned* b) {
    asm volatile(
        "mma.sync.aligned.m16n8k8.row.col.f32.tf32.tf32.f32 "
        "{%0,%1,%2,%3}, {%4,%5,%6,%7}, {%8,%9}, {%0,%1,%2,%3};"
        : "+f"(c[0]), "+f"(c[1]), "+f"(c[2]), "+f"(c[3])
        : "r"(a[0]), "r"(a[1]), "r"(a[2]), "r"(a[3]), "r"(b[0]), "r"(b[1]));
}

// ============================================================
// K1: xbar[b,c,v] = mean_t x[b,c,t,v].  grid = B*C, block = 128
// Block 0 additionally pre-rounds W3 -> g_w3t (consumed by k4).
// ============================================================
__global__ void k1_xbar(const float* __restrict__ x, const float* __restrict__ W3) {
    __shared__ __align__(16) float xs[Tt * Vv];
    __shared__ float part[5][Vv];
    int bc = blockIdx.x, tid = threadIdx.x;
    if (bc == 0) {
        for (int idx = tid; idx < OUTo * Cc; idx += 128)
            g_w3t[idx] = __float_as_uint(to_tf32(W3[idx]));
    }
    const float4* xg4 = reinterpret_cast<const float4*>(x + (size_t)bc * (Tt * Vv));
    float4* xs4 = reinterpret_cast<float4*>(xs);
    for (int f = tid; f < Tt * Vv / 4; f += 128) xs4[f] = xg4[f];
    __syncthreads();
    if (tid < 125) {
        int v = tid % 25, s = tid / 25;
        int t0 = s * 26;
        int t1 = t0 + 26; if (t1 > Tt) t1 = Tt;
        float acc = 0.f;
        for (int t = t0; t < t1; t++) acc += xs[t * Vv + v];
        part[s][v] = acc;
    }
    __syncthreads();
    if (tid < Vv) {
        float acc = part[0][tid] + part[1][tid] + part[2][tid] + part[3][tid] + part[4][tid];
        g_xbar[bc * Vv + tid] = acc * (1.f / (float)Tt);
    }
}

// ============================================================
// K2: rel[b,r,i,j] = tanh(x1[b,r,i] - x2[b,r,j]).  grid = B, block = 256
// ============================================================
__global__ void k2_rel(const float* __restrict__ W1, const float* __restrict__ b1,
                       const float* __restrict__ W2, const float* __restrict__ b2) {
    __shared__ float xb[Cc * Vv];
    __shared__ float w1s[Rr * Cc], w2s[Rr * Cc];
    __shared__ float x1s[Rr * Vv], x2s[Rr * Vv];
    __shared__ float b1s[Rr], b2s[Rr];
    int b = blockIdx.x, tid = threadIdx.x;
    for (int idx = tid; idx < Cc * Vv; idx += 256) xb[idx] = g_xbar[b * (Cc * Vv) + idx];
    for (int idx = tid; idx < Rr * Cc; idx += 256) { w1s[idx] = W1[idx]; w2s[idx] = W2[idx]; }
    if (tid < Rr) { b1s[tid] = b1[tid]; b2s[tid] = b2[tid]; }
    __syncthreads();
    if (tid < Rr * Vv) {
        int r = tid / Vv, v = tid % Vv;
        float a1 = b1s[r], a2 = b2s[r];
        #pragma unroll 8
        for (int c = 0; c < Cc; c++) {
            float xv = xb[c * Vv + v];
            a1 = fmaf(w1s[r * Cc + c], xv, a1);
            a2 = fmaf(w2s[r * Cc + c], xv, a2);
        }
        x1s[tid] = a1; x2s[tid] = a2;
    }
    __syncthreads();
    for (int idx = tid; idx < Rr * Vv * Vv; idx += 256) {
        int r = idx / (Vv * Vv), rem = idx % (Vv * Vv);
        int i = rem / Vv, j = rem % Vv;
        g_rel[b * (Rr * Vv * Vv) + idx] = tanhf(x1s[r * Vv + i] - x2s[r * Vv + j]);
    }
}

// ============================================================
// K3 (tensor-core): per (b,c) block, 128 threads = 4 warps,
// 2m x 4n per warp (proven best shape — round-12 winner, unchanged).
// GEMM: z[t][i] = sum_col xtap[t][col]*BT[i][col], col = k*28+v;
// xtap[t][col] = xp_flat[t*28+col] (free im2col).
// BT 26 rows (pad rows share zero row 25).  smem ~42.7KB, 5 blocks/SM.
// ============================================================
#define VP 28
#define KK 256
#define BTS 260                   // BT row stride (floats)
#define BTN 26                    // 25 real rows + 1 shared zero row
#define XPF 3840                  // xp flat floats

__global__ __launch_bounds__(128) void k3_z(const float* __restrict__ x,
                                            const float* __restrict__ A,
                                            const float* __restrict__ W4,
                                            const float* __restrict__ b4) {
    __shared__ __align__(16) float BT[BTN * BTS];  // [i][col], row 25 = zeros
    __shared__ __align__(16) float xp[XPF];        // flat [(t+8)*28 + v]
    __shared__ float w4s[TSs * Rr];
    __shared__ float b4s[TSs];

    int bc = blockIdx.x;
    int b = bc >> 6, c = bc & 63;
    int tid = threadIdx.x;

    if (tid < TSs * Rr) w4s[tid] = W4[c * (TSs * Rr) + tid];
    if (tid < TSs) b4s[tid] = b4[c * TSs + tid];

    // ---- fill xp first (earliest LDG issue) ----
    const float* xg = x + (size_t)bc * (Tt * Vv);
    for (int idx = tid; idx < Tt * Vv; idx += 128) {
        int t = idx / Vv, v = idx - t * Vv;
        xp[(t + TSs - 1) * VP + v] = to_tf32(xg[idx]);
    }

    // ---- selective zeroing of pad regions ----
    for (int idx = tid; idx < BTS; idx += 128) BT[25 * BTS + idx] = 0.f;  // zero row
    for (int idx = tid; idx < 25 * 27; idx += 128) {                      // v-pad cols
        int i = idx / 27, r = idx - i * 27;
        int k = r / 3, j = r - k * 3;
        BT[i * BTS + k * VP + Vv + j] = 0.f;
    }
    for (int idx = tid; idx < 25 * 4; idx += 128) {                       // cols 252..255
        int i = idx >> 2, j = idx & 3;
        BT[i * BTS + 252 + j] = 0.f;
    }
    for (int idx = tid; idx < 8 * VP; idx += 128) xp[idx] = 0.f;          // causal head
    for (int idx = tid; idx < 128 * 3; idx += 128) {                      // xp v-pads
        int t = 8 + idx / 3, j = idx - (idx / 3) * 3;
        xp[t * VP + Vv + j] = 0.f;
    }
    for (int idx = tid; idx < 32; idx += 128) xp[3808 + idx] = 0.f;       // tail
    __syncthreads();   // w4s/b4s + pad zeros visible

    // ---- build BT[i][k*28+v] = Adyn_k[v][i] (tf32-rounded), i<25 only ----
    const float* relg = g_rel + b * (Rr * Vv * Vv);
    for (int vi = tid; vi < Vv * Vv; vi += 128) {
        float r8[Rr];
        #pragma unroll
        for (int r = 0; r < Rr; r++) r8[r] = __ldg(&relg[r * (Vv * Vv) + vi]);
        float av = __ldg(&A[vi]);
        int v = vi / Vv, i = vi - v * Vv;
        #pragma unroll
        for (int k = 0; k < TSs; k++) {
            float acc = b4s[k] + av;
            #pragma unroll
            for (int r = 0; r < Rr; r++) acc = fmaf(w4s[k * Rr + r], r8[r], acc);
            BT[i * BTS + k * VP + v] = to_tf32(acc);
        }
    }
    __syncthreads();

    // ---- MMA mainloop: warp w -> t in [32w, 32w+32), 2 m16 x 4 n8 ----
    int w = tid >> 5, lane = tid & 31;
    int g = lane >> 2, tig = lane & 3;
    int t0 = w * 32;

    int baseN[4];
    #pragma unroll
    for (int n = 0; n < 4; n++) {
        int row = n * 8 + g;
        if (row > 25) row = 25;           // pad rows share zero row 25
        baseN[n] = row * BTS;
    }

    float cfr[2][4][4];
    #pragma unroll
    for (int m = 0; m < 2; m++)
        #pragma unroll
        for (int n = 0; n < 4; n++)
            #pragma unroll
            for (int e = 0; e < 4; e++) cfr[m][n][e] = 0.f;

    const unsigned* xpu = reinterpret_cast<const unsigned*>(xp);
    const unsigned* btu = reinterpret_cast<const unsigned*>(BT);

    #pragma unroll 4
    for (int ks = 0; ks < KK / 8; ks++) {
        int kb = ks * 8;
        unsigned afr[2][4];
        #pragma unroll
        for (int m = 0; m < 2; m++) {
            int r0 = (t0 + m * 16 + g) * VP + kb + tig;
            afr[m][0] = xpu[r0];
            afr[m][1] = xpu[r0 + 8 * VP];
            afr[m][2] = xpu[r0 + 4];
            afr[m][3] = xpu[r0 + 8 * VP + 4];
        }
        unsigned bfr[4][2];
        #pragma unroll
        for (int n = 0; n < 4; n++) {
            int rb = baseN[n] + kb + tig;
            bfr[n][0] = btu[rb];
            bfr[n][1] = btu[rb + 4];
        }
        #pragma unroll
        for (int m = 0; m < 2; m++)
            #pragma unroll
            for (int n = 0; n < 4; n++)
                mma_tf32(cfr[m][n], afr[m], bfr[n]);
    }
    __syncthreads();               // done reading xp; alias as zstage

    // ---- write C frags (tf32-rounded) to zstage [t][25], then copy out ----
    float* zst = xp;
    #pragma unroll
    for (int m = 0; m < 2; m++) {
        int tr = t0 + m * 16 + g;
        #pragma unroll
        for (int n = 0; n < 4; n++) {
            int i0 = n * 8 + 2 * tig;
            if (i0 < Vv) {
                zst[tr * Vv + i0]       = to_tf32(cfr[m][n][0]);
                zst[(tr + 8) * Vv + i0] = to_tf32(cfr[m][n][2]);
            }
            if (i0 + 1 < Vv) {
                zst[tr * Vv + i0 + 1]       = to_tf32(cfr[m][n][1]);
                zst[(tr + 8) * Vv + i0 + 1] = to_tf32(cfr[m][n][3]);
            }
        }
    }
    __syncthreads();
    float4* zg4 = reinterpret_cast<float4*>(g_z + (size_t)bc * (Tt * Vv));
    const float4* zs4 = reinterpret_cast<const float4*>(zst);
    for (int f = tid; f < Tt * Vv / 4; f += 128) zg4[f] = zs4[f];
}

// ============================================================
// K4 (tensor-core): out[b,o,n] = b3[o] + sum_c W3[o,c] * z[b,c,n]
// 128 threads (4 warps), n-tile 64, grid 3200, K = c = 64 via 4
// upfront cp.async chunks of 16 (warp-private slices).
// NO W3 smem staging: B-frags stream via __ldg from g_w3t (16KB,
// L1/L2-resident, pre-rounded tf32) — removes 4096 LDG+CVT+STS per
// block and the covering barrier.  smem 18.7KB + regs<=64 ->
// 8 blocks/SM (32 warps).  Each warp touches only pool cols
// [16w,16w+16) until the final store, so __syncwarp suffices.
// NSS=72 (== 8 mod 32): A-frag banks 8*tig+g conflict-free.
// ============================================================
#define NSS 72
#define K4_POOLF (4 * 16 * NSS)   // 4608 floats = 18432 B

__global__ __launch_bounds__(128, 8) void k4_mma(const float* __restrict__ b3,
                                                 float* __restrict__ out) {
    __shared__ __align__(16) float pool[K4_POOLF];
    __shared__ float b3s[OUTo];
    float* zsb = pool;                          // zs[ci] = zsb + ci*16*NSS

    int nt = blockIdx.x, b = blockIdx.y;        // nt in [0,50)
    int tid = threadIdx.x;
    int w = tid >> 5, lane = tid & 31;
    int nw = w * 16;

    // ---- warp-private issue: warp w loads cols [nw,nw+16) of all rows ----
    const float* zbase = g_z + (size_t)b * (Cc * Tt * Vv) + nt * 64;
    #pragma unroll
    for (int ci = 0; ci < 4; ci++) {
        float* dst = zsb + ci * 16 * NSS;
        #pragma unroll
        for (int rep = 0; rep < 2; rep++) {
            int idx = lane + rep * 32;          // 0..63
            int row = idx >> 2, s4 = idx & 3;   // 16 rows x 4 float4-cols
            cp_async16(&dst[row * NSS + nw + s4 * 4],
                       zbase + (size_t)(ci * 16 + row) * (Tt * Vv) + nw + s4 * 4);
        }
        asm volatile("cp.async.commit_group;\n" ::: "memory");
    }

    if (tid < OUTo) b3s[tid] = b3[tid];

    int g = lane >> 2, tig = lane & 3;

    float cfr[8][4];
    #pragma unroll
    for (int ot = 0; ot < 8; ot++)
        #pragma unroll
        for (int e = 0; e < 4; e++) cfr[ot][e] = 0.f;

    auto compute = [&](int ci) {
        const unsigned* zbu = reinterpret_cast<const unsigned*>(zsb + ci * 16 * NSS);
        #pragma unroll
        for (int ks = 0; ks < 2; ks++) {
            int kb = ks * 8;
            unsigned afr[4];
            afr[0] = zbu[(kb + tig) * NSS + nw + g];
            afr[1] = zbu[(kb + tig) * NSS + nw + g + 8];
            afr[2] = zbu[(kb + tig + 4) * NSS + nw + g];
            afr[3] = zbu[(kb + tig + 4) * NSS + nw + g + 8];
            int cg = ci * 16 + kb;
            #pragma unroll
            for (int ot = 0; ot < 8; ot++) {
                unsigned bfr[2];
                bfr[0] = __ldg(&g_w3t[(ot * 8 + g) * Cc + cg + tig]);
                bfr[1] = __ldg(&g_w3t[(ot * 8 + g) * Cc + cg + tig + 4]);
                mma_tf32(cfr[ot], afr, bfr);
            }
        }
    };

    // warp-local pipeline: each warp consumes only its own cp.asyncs
    wait_group<3>(); __syncwarp(); compute(0);
    wait_group<2>(); __syncwarp(); compute(1);
    wait_group<1>(); __syncwarp(); compute(2);
    wait_group<0>(); __syncwarp(); compute(3);
    __syncwarp();                  // own-stripe reads done before stage alias

    // ---- stage frags into pool (own col-stripe) as stage[o][n] ----
    float* stage = pool;
    #pragma unroll
    for (int ot = 0; ot < 8; ot++) {
        int oA = ot * 8 + 2 * tig, oB = oA + 1;
        stage[oA * NSS + nw + g]     = cfr[ot][0];
        stage[oB * NSS + nw + g]     = cfr[ot][1];
        stage[oA * NSS + nw + g + 8] = cfr[ot][2];
        stage[oB * NSS + nw + g + 8] = cfr[ot][3];
    }
    __syncthreads();               // cross-warp: full stage + b3s visible

    // ---- coalesced stores with bias add (64 o rows x 64 n) ----
    float* ob = out + (size_t)b * (OUTo * Tt * Vv) + (size_t)nt * 64;
    for (int f = tid; f < OUTo * 16; f += 128) {
        int row = f >> 4, seg = f & 15;
        float4 v = *reinterpret_cast<const float4*>(&stage[row * NSS + seg * 4]);
        float bb = b3s[row];
        v.x += bb; v.y += bb; v.z += bb; v.w += bb;
        *reinterpret_cast<float4*>(ob + (size_t)row * (Tt * Vv) + seg * 4) = v;
    }
}

// ============================================================
extern "C" void kernel_launch(void* const* d_in, const int* in_sizes, int n_in,
                              void* d_out, int out_size) {
    const float* x  = (const float*)d_in[0];
    const float* A  = (const float*)d_in[1];
    const float* W1 = (const float*)d_in[2];
    const float* b1 = (const float*)d_in[3];
    const float* W2 = (const float*)d_in[4];
    const float* b2 = (const float*)d_in[5];
    const float* W4 = (const float*)d_in[6];
    const float* b4 = (const float*)d_in[7];
    const float* W3 = (const float*)d_in[8];
    const float* b3 = (const float*)d_in[9];
    float* out = (float*)d_out;

    k1_xbar<<<Bb * Cc, 128>>>(x, W3);
    k2_rel<<<Bb, 256>>>(W1, b1, W2, b2);
    k3_z<<<Bb * Cc, 128>>>(x, A, W4, b4);
    k4_mma<<<dim3(50, Bb), 128>>>(b3, out);
}

// round 16
// speedup vs baseline: 1.2827x; 1.2827x over previous
#include <cuda_runtime.h>
#include <cstdint>

// Problem constants
#define Bb 64
#define Cc 64
#define Tt 128
#define Vv 25
#define Rr 8
#define TSs 9
#define OUTo 64

typedef unsigned long long ull;

// Scratch (device globals — no allocation allowed)
__device__ float g_xbar[Bb * Cc * Vv];          // (b,c,v) mean over t
__device__ float g_rel[Bb * Rr * Vv * Vv];      // (b,r,vi)
__device__ float g_z[Bb * Cc * Tt * Vv];        // (b,c,t,v), tf32-rounded

// ---------- helpers ----------
__device__ __forceinline__ void cp_async16(float* smem_dst, const float* gmem_src) {
    unsigned s = (unsigned)__cvta_generic_to_shared(smem_dst);
    asm volatile("cp.async.cg.shared.global [%0], [%1], 16;\n" :: "r"(s), "l"(gmem_src));
}
template <int N> __device__ __forceinline__ void wait_group() {
    asm volatile("cp.async.wait_group %0;\n" :: "n"(N) : "memory");
}
__device__ __forceinline__ float to_tf32(float x) {
    unsigned u;
    asm("cvt.rna.tf32.f32 %0, %1;" : "=r"(u) : "f"(x));
    return __uint_as_float(u);
}
__device__ __forceinline__ void mma_tf32(float* c, const unsigned* a, const unsigned* b) {
    asm volatile(
        "mma.sync.aligned.m16n8k8.row.col.f32.tf32.tf32.f32 "
        "{%0,%1,%2,%3}, {%4,%5,%6,%7}, {%8,%9}, {%0,%1,%2,%3};"
        : "+f"(c[0]), "+f"(c[1]), "+f"(c[2]), "+f"(c[3])
        : "r"(a[0]), "r"(a[1]), "r"(a[2]), "r"(a[3]), "r"(b[0]), "r"(b[1]));
}

// ============================================================
// K1: xbar[b,c,v] = mean_t x[b,c,t,v].  grid = B*C, block = 128
// ============================================================
__global__ void k1_xbar(const float* __restrict__ x) {
    __shared__ __align__(16) float xs[Tt * Vv];
    __shared__ float part[5][Vv];
    int bc = blockIdx.x, tid = threadIdx.x;
    const float4* xg4 = reinterpret_cast<const float4*>(x + (size_t)bc * (Tt * Vv));
    float4* xs4 = reinterpret_cast<float4*>(xs);
    for (int f = tid; f < Tt * Vv / 4; f += 128) xs4[f] = xg4[f];
    __syncthreads();
    if (tid < 125) {
        int v = tid % 25, s = tid / 25;
        int t0 = s * 26;
        int t1 = t0 + 26; if (t1 > Tt) t1 = Tt;
        float acc = 0.f;
        for (int t = t0; t < t1; t++) acc += xs[t * Vv + v];
        part[s][v] = acc;
    }
    __syncthreads();
    if (tid < Vv) {
        float acc = part[0][tid] + part[1][tid] + part[2][tid] + part[3][tid] + part[4][tid];
        g_xbar[bc * Vv + tid] = acc * (1.f / (float)Tt);
    }
}

// ============================================================
// K2: rel[b,r,i,j] = tanh(x1[b,r,i] - x2[b,r,j]).  grid = B, block = 256
// ============================================================
__global__ void k2_rel(const float* __restrict__ W1, const float* __restrict__ b1,
                       const float* __restrict__ W2, const float* __restrict__ b2) {
    __shared__ float xb[Cc * Vv];
    __shared__ float w1s[Rr * Cc], w2s[Rr * Cc];
    __shared__ float x1s[Rr * Vv], x2s[Rr * Vv];
    __shared__ float b1s[Rr], b2s[Rr];
    int b = blockIdx.x, tid = threadIdx.x;
    for (int idx = tid; idx < Cc * Vv; idx += 256) xb[idx] = g_xbar[b * (Cc * Vv) + idx];
    for (int idx = tid; idx < Rr * Cc; idx += 256) { w1s[idx] = W1[idx]; w2s[idx] = W2[idx]; }
    if (tid < Rr) { b1s[tid] = b1[tid]; b2s[tid] = b2[tid]; }
    __syncthreads();
    if (tid < Rr * Vv) {
        int r = tid / Vv, v = tid % Vv;
        float a1 = b1s[r], a2 = b2s[r];
        #pragma unroll 8
        for (int c = 0; c < Cc; c++) {
            float xv = xb[c * Vv + v];
            a1 = fmaf(w1s[r * Cc + c], xv, a1);
            a2 = fmaf(w2s[r * Cc + c], xv, a2);
        }
        x1s[tid] = a1; x2s[tid] = a2;
    }
    __syncthreads();
    for (int idx = tid; idx < Rr * Vv * Vv; idx += 256) {
        int r = idx / (Vv * Vv), rem = idx % (Vv * Vv);
        int i = rem / Vv, j = rem % Vv;
        g_rel[b * (Rr * Vv * Vv) + idx] = tanhf(x1s[r * Vv + i] - x2s[r * Vv + j]);
    }
}

// ============================================================
// K3 (tensor-core): per (b,c) block, 128 threads = 4 warps,
// 2m x 4n per warp (round-12 winner; mainloop FROZEN).
// GEMM: z[t][i] = sum_col xtap[t][col]*BT[i][col], col = k*28+v;
// xtap[t][col] = xp_flat[t*28+col] (free im2col).
// BT 26 rows (pad rows share zero row 25).  smem ~42.7KB, 5 blocks/SM.
// Build change (r16): 2 vi per iteration — each broadcast w4s LDS
// feeds 2 FMAs (build LDS halved); per-vi FMA chain bit-identical.
// ============================================================
#define VP 28
#define KK 256
#define BTS 260                   // BT row stride (floats)
#define BTN 26                    // 25 real rows + 1 shared zero row
#define XPF 3840                  // xp flat floats

__global__ __launch_bounds__(128) void k3_z(const float* __restrict__ x,
                                            const float* __restrict__ A,
                                            const float* __restrict__ W4,
                                            const float* __restrict__ b4) {
    __shared__ __align__(16) float BT[BTN * BTS];  // [i][col], row 25 = zeros
    __shared__ __align__(16) float xp[XPF];        // flat [(t+8)*28 + v]
    __shared__ float w4s[TSs * Rr];
    __shared__ float b4s[TSs];

    int bc = blockIdx.x;
    int b = bc >> 6, c = bc & 63;
    int tid = threadIdx.x;

    if (tid < TSs * Rr) w4s[tid] = W4[c * (TSs * Rr) + tid];
    if (tid < TSs) b4s[tid] = b4[c * TSs + tid];

    // ---- fill xp first (earliest LDG issue) ----
    const float* xg = x + (size_t)bc * (Tt * Vv);
    for (int idx = tid; idx < Tt * Vv; idx += 128) {
        int t = idx / Vv, v = idx - t * Vv;
        xp[(t + TSs - 1) * VP + v] = to_tf32(xg[idx]);
    }

    // ---- selective zeroing of pad regions ----
    for (int idx = tid; idx < BTS; idx += 128) BT[25 * BTS + idx] = 0.f;  // zero row
    for (int idx = tid; idx < 25 * 27; idx += 128) {                      // v-pad cols
        int i = idx / 27, r = idx - i * 27;
        int k = r / 3, j = r - k * 3;
        BT[i * BTS + k * VP + Vv + j] = 0.f;
    }
    for (int idx = tid; idx < 25 * 4; idx += 128) {                       // cols 252..255
        int i = idx >> 2, j = idx & 3;
        BT[i * BTS + 252 + j] = 0.f;
    }
    for (int idx = tid; idx < 8 * VP; idx += 128) xp[idx] = 0.f;          // causal head
    for (int idx = tid; idx < 128 * 3; idx += 128) {                      // xp v-pads
        int t = 8 + idx / 3, j = idx - (idx / 3) * 3;
        xp[t * VP + Vv + j] = 0.f;
    }
    for (int idx = tid; idx < 32; idx += 128) xp[3808 + idx] = 0.f;       // tail
    __syncthreads();   // w4s/b4s + pad zeros visible

    // ---- build BT[i][k*28+v] = Adyn_k[v][i], 2 vi per iteration ----
    const float* relg = g_rel + b * (Rr * Vv * Vv);
    for (int p = tid; p < 313; p += 128) {
        int vi0 = 2 * p, vi1 = 2 * p + 1;
        bool has1 = (vi1 < Vv * Vv);
        float r8a[Rr], r8b[Rr];
        #pragma unroll
        for (int r = 0; r < Rr; r++) {
            r8a[r] = __ldg(&relg[r * (Vv * Vv) + vi0]);
            r8b[r] = has1 ? __ldg(&relg[r * (Vv * Vv) + vi1]) : 0.f;
        }
        float ava = __ldg(&A[vi0]);
        float avb = has1 ? __ldg(&A[vi1]) : 0.f;
        int v0 = vi0 / Vv, i0 = vi0 - v0 * Vv;
        int v1 = vi1 / Vv, i1 = vi1 - v1 * Vv;
        #pragma unroll
        for (int k = 0; k < TSs; k++) {
            float bb = b4s[k];
            float acca = bb + ava;
            float accb = bb + avb;
            #pragma unroll
            for (int r = 0; r < Rr; r++) {
                float wv = w4s[k * Rr + r];       // one broadcast LDS, two FMAs
                acca = fmaf(wv, r8a[r], acca);
                accb = fmaf(wv, r8b[r], accb);
            }
            BT[i0 * BTS + k * VP + v0] = to_tf32(acca);
            if (has1) BT[i1 * BTS + k * VP + v1] = to_tf32(accb);
        }
    }
    __syncthreads();

    // ---- MMA mainloop: warp w -> t in [32w, 32w+32), 2 m16 x 4 n8 ----
    int w = tid >> 5, lane = tid & 31;
    int g = lane >> 2, tig = lane & 3;
    int t0 = w * 32;

    int baseN[4];
    #pragma unroll
    for (int n = 0; n < 4; n++) {
        int row = n * 8 + g;
        if (row > 25) row = 25;           // pad rows share zero row 25
        baseN[n] = row * BTS;
    }

    float cfr[2][4][4];
    #pragma unroll
    for (int m = 0; m < 2; m++)
        #pragma unroll
        for (int n = 0; n < 4; n++)
            #pragma unroll
            for (int e = 0; e < 4; e++) cfr[m][n][e] = 0.f;

    const unsigned* xpu = reinterpret_cast<const unsigned*>(xp);
    const unsigned* btu = reinterpret_cast<const unsigned*>(BT);

    #pragma unroll 4
    for (int ks = 0; ks < KK / 8; ks++) {
        int kb = ks * 8;
        unsigned afr[2][4];
        #pragma unroll
        for (int m = 0; m < 2; m++) {
            int r0 = (t0 + m * 16 + g) * VP + kb + tig;
            afr[m][0] = xpu[r0];
            afr[m][1] = xpu[r0 + 8 * VP];
            afr[m][2] = xpu[r0 + 4];
            afr[m][3] = xpu[r0 + 8 * VP + 4];
        }
        unsigned bfr[4][2];
        #pragma unroll
        for (int n = 0; n < 4; n++) {
            int rb = baseN[n] + kb + tig;
            bfr[n][0] = btu[rb];
            bfr[n][1] = btu[rb + 4];
        }
        #pragma unroll
        for (int m = 0; m < 2; m++)
            #pragma unroll
            for (int n = 0; n < 4; n++)
                mma_tf32(cfr[m][n], afr[m], bfr[n]);
    }
    __syncthreads();               // done reading xp; alias as zstage

    // ---- write C frags (tf32-rounded) to zstage [t][25], then copy out ----
    float* zst = xp;
    #pragma unroll
    for (int m = 0; m < 2; m++) {
        int tr = t0 + m * 16 + g;
        #pragma unroll
        for (int n = 0; n < 4; n++) {
            int i0 = n * 8 + 2 * tig;
            if (i0 < Vv) {
                zst[tr * Vv + i0]       = to_tf32(cfr[m][n][0]);
                zst[(tr + 8) * Vv + i0] = to_tf32(cfr[m][n][2]);
            }
            if (i0 + 1 < Vv) {
                zst[tr * Vv + i0 + 1]       = to_tf32(cfr[m][n][1]);
                zst[(tr + 8) * Vv + i0 + 1] = to_tf32(cfr[m][n][3]);
            }
        }
    }
    __syncthreads();
    float4* zg4 = reinterpret_cast<float4*>(g_z + (size_t)bc * (Tt * Vv));
    const float4* zs4 = reinterpret_cast<const float4*>(zst);
    for (int f = tid; f < Tt * Vv / 4; f += 128) zg4[f] = zs4[f];
}

// ============================================================
// K4 (tensor-core): out[b,o,n] = b3[o] + sum_c W3[o,c] * z[b,c,n]
// Round-13/14 version EXACTLY (best measured: 29.57us).
// 128 threads (4 warps), n-tile 64, grid 3200, K = c = 64 via 4
// upfront cp.async chunks of 16 (warp-private slices); W3 staged in
// smem (broadcast LDS >> scattered __ldg, r15 lesson).
// NSS=72 (== 8 mod 32): A-frag banks 8*tig+g conflict-free.
// W3S=68 (== 4 mod 32): B-frag banks 4*g+tig conflict-free.
// ============================================================
#define NSS 72
#define W3S 68
#define K4_POOLF (OUTo * W3S + 4 * 16 * NSS)   // 4352 + 4608 = 8960 floats

__global__ __launch_bounds__(128, 8) void k4_mma(const float* __restrict__ W3,
                                                 const float* __restrict__ b3,
                                                 float* __restrict__ out) {
    __shared__ __align__(16) float pool[K4_POOLF];
    __shared__ float b3s[OUTo];
    float* w3s = pool;                          // [o][c] stride 68
    float* zsb = pool + OUTo * W3S;             // zs[ci] = zsb + ci*16*NSS

    int nt = blockIdx.x, b = blockIdx.y;        // nt in [0,50)
    int tid = threadIdx.x;
    int w = tid >> 5, lane = tid & 31;
    int nw = w * 16;

    // ---- warp-private issue: warp w loads cols [nw,nw+16) of all rows ----
    const float* zbase = g_z + (size_t)b * (Cc * Tt * Vv) + nt * 64;
    #pragma unroll
    for (int ci = 0; ci < 4; ci++) {
        float* dst = zsb + ci * 16 * NSS;
        #pragma unroll
        for (int rep = 0; rep < 2; rep++) {
            int idx = lane + rep * 32;          // 0..63
            int row = idx >> 2, s4 = idx & 3;   // 16 rows x 4 float4-cols
            cp_async16(&dst[row * NSS + nw + s4 * 4],
                       zbase + (size_t)(ci * 16 + row) * (Tt * Vv) + nw + s4 * 4);
        }
        asm volatile("cp.async.commit_group;\n" ::: "memory");
    }

    // stage W3 (tf32) + b3 while z loads fly
    for (int idx = tid; idx < OUTo * Cc; idx += 128) {
        int o = idx >> 6, c = idx & 63;
        w3s[o * W3S + c] = to_tf32(W3[idx]);
    }
    if (tid < OUTo) b3s[tid] = b3[tid];
    __syncthreads();               // w3s/b3s visible to all warps

    int g = lane >> 2, tig = lane & 3;

    float cfr[8][4];
    #pragma unroll
    for (int ot = 0; ot < 8; ot++)
        #pragma unroll
        for (int e = 0; e < 4; e++) cfr[ot][e] = 0.f;

    const unsigned* wtu = reinterpret_cast<const unsigned*>(w3s);
    auto compute = [&](int ci) {
        const unsigned* zbu = reinterpret_cast<const unsigned*>(zsb + ci * 16 * NSS);
        #pragma unroll
        for (int ks = 0; ks < 2; ks++) {
            int kb = ks * 8;
            unsigned afr[4];
            afr[0] = zbu[(kb + tig) * NSS + nw + g];
            afr[1] = zbu[(kb + tig) * NSS + nw + g + 8];
            afr[2] = zbu[(kb + tig + 4) * NSS + nw + g];
            afr[3] = zbu[(kb + tig + 4) * NSS + nw + g + 8];
            int cg = ci * 16 + kb;
            #pragma unroll
            for (int ot = 0; ot < 8; ot++) {
                unsigned bfr[2];
                bfr[0] = wtu[(ot * 8 + g) * W3S + cg + tig];
                bfr[1] = wtu[(ot * 8 + g) * W3S + cg + tig + 4];
                mma_tf32(cfr[ot], afr, bfr);
            }
        }
    };

    // warp-local pipeline: each warp consumes only its own cp.asyncs
    wait_group<3>(); __syncwarp(); compute(0);
    wait_group<2>(); __syncwarp(); compute(1);
    wait_group<1>(); __syncwarp(); compute(2);
    wait_group<0>(); __syncwarp(); compute(3);
    __syncthreads();               // all reads of pool done before stage alias

    // ---- stage frags into pool (now dead) as stage[o][n], stride NSS ----
    float* stage = pool;
    #pragma unroll
    for (int ot = 0; ot < 8; ot++) {
        int oA = ot * 8 + 2 * tig, oB = oA + 1;
        stage[oA * NSS + nw + g]     = cfr[ot][0];
        stage[oB * NSS + nw + g]     = cfr[ot][1];
        stage[oA * NSS + nw + g + 8] = cfr[ot][2];
        stage[oB * NSS + nw + g + 8] = cfr[ot][3];
    }
    __syncthreads();

    // ---- coalesced stores with bias add (64 o rows x 64 n) ----
    float* ob = out + (size_t)b * (OUTo * Tt * Vv) + (size_t)nt * 64;
    for (int f = tid; f < OUTo * 16; f += 128) {
        int row = f >> 4, seg = f & 15;
        float4 v = *reinterpret_cast<const float4*>(&stage[row * NSS + seg * 4]);
        float bb = b3s[row];
        v.x += bb; v.y += bb; v.z += bb; v.w += bb;
        *reinterpret_cast<float4*>(ob + (size_t)row * (Tt * Vv) + seg * 4) = v;
    }
}

// ============================================================
extern "C" void kernel_launch(void* const* d_in, const int* in_sizes, int n_in,
                              void* d_out, int out_size) {
    const float* x  = (const float*)d_in[0];
    const float* A  = (const float*)d_in[1];
    const float* W1 = (const float*)d_in[2];
    const float* b1 = (const float*)d_in[3];
    const float* W2 = (const float*)d_in[4];
    const float* b2 = (const float*)d_in[5];
    const float* W4 = (const float*)d_in[6];
    const float* b4 = (const float*)d_in[7];
    const float* W3 = (const float*)d_in[8];
    const float* b3 = (const float*)d_in[9];
    float* out = (float*)d_out;

    k1_xbar<<<Bb * Cc, 128>>>(x);
    k2_rel<<<Bb, 256>>>(W1, b1, W2, b2);
    k3_z<<<Bb * Cc, 128>>>(x, A, W4, b4);
    k4_mma<<<dim3(50, Bb), 128>>>(W3, b3, out);
}